// round 8
// baseline (speedup 1.0000x reference)
#include <cuda_runtime.h>

typedef unsigned long long ull;

// Plain-transposed weights in global (built per replay by setup_kernel).
__device__ float g_WT[2][256 * 64];  // [k][c]  (0: Wfp1, 1: Wf1)
__device__ float g_WngT[128 * 64];   // [k][c]

__global__ void setup_kernel(const float* __restrict__ Wfp1,
                             const float* __restrict__ Wf1,
                             const float* __restrict__ Wng) {
    int tid = blockIdx.x * blockDim.x + threadIdx.x;
    int stride = gridDim.x * blockDim.x;
    for (int i = tid; i < 64 * 256; i += stride) {
        int c = i >> 8, k = i & 255;
        g_WT[0][k * 64 + c] = Wfp1[i];
        g_WT[1][k * 64 + c] = Wf1[i];
    }
    for (int i = tid; i < 64 * 128; i += stride) {
        int c = i >> 7, k = i & 127;
        g_WngT[k * 64 + c] = Wng[i];
    }
}

__device__ __forceinline__ float sigmoidf_(float x) {
    return __fdividef(1.0f, 1.0f + __expf(-x));
}
__device__ __forceinline__ float gatef_(float x, float rm) {
    return x * sigmoidf_(fabsf(x - rm));
}
__device__ __forceinline__ float leakyf_(float x) {
    return x > 0.0f ? x : 0.01f * x;
}
__device__ __forceinline__ void ffma2_(ull& d, ull a, ull b) {
    asm("fma.rn.f32x2 %0, %1, %2, %0;" : "+l"(d) : "l"(a), "l"(b));
}
__device__ __forceinline__ ull fmul2_(ull a, ull b) {
    ull r;
    asm("mul.rn.f32x2 %0, %1, %2;" : "=l"(r) : "l"(a), "l"(b));
    return r;
}
__device__ __forceinline__ ull dup2_(float x) {
    ull r;
    unsigned u = __float_as_uint(x);
    asm("mov.b64 %0, {%1, %1};" : "=l"(r) : "r"(u));
    return r;
}
__device__ __forceinline__ float2 unpk_(ull v) {
    float2 r;
    asm("mov.b64 {%0, %1}, %2;" : "=f"(r.x), "=f"(r.y) : "l"(v));
    return r;
}
__device__ __forceinline__ void st_dup2(float* p, float v) {
    *reinterpret_cast<float2*>(p) = make_float2(v, v);
}

__device__ __forceinline__ void copy16(float* __restrict__ dst,
                                       const float* __restrict__ src, int tid) {
    const float4* s = reinterpret_cast<const float4*>(src);
    float4* d = reinterpret_cast<float4*>(dst);
#pragma unroll
    for (int i = 0; i < 16; i++) d[tid + i * 256] = s[tid + i * 256];
}
__device__ __forceinline__ void copy8(float* __restrict__ dst,
                                      const float* __restrict__ src, int tid) {
    const float4* s = reinterpret_cast<const float4*>(src);
    float4* d = reinterpret_cast<float4*>(dst);
#pragma unroll
    for (int i = 0; i < 8; i++) d[tid + i * 256] = s[tid + i * 256];
}

// One 4-output matvec + sigmoid. Thread handles outputs q*4..q*4+3.
__device__ __forceinline__ void mv4(const float* __restrict__ in, int row,
                                    const float* __restrict__ W,
                                    const float* __restrict__ b, int q,
                                    float h[4]) {
    ull acc[4] = {0, 0, 0, 0};
#pragma unroll 4
    for (int k = 0; k < 64; k += 4) {
        ulonglong2 xv =
            __ldg(reinterpret_cast<const ulonglong2*>(in + row * 64 + k));
#pragma unroll
        for (int j = 0; j < 4; j++) {
            ulonglong2 w = __ldg(
                reinterpret_cast<const ulonglong2*>(W + (q * 4 + j) * 64 + k));
            ffma2_(acc[j], xv.x, w.x);
            ffma2_(acc[j], xv.y, w.y);
        }
    }
#pragma unroll
    for (int j = 0; j < 4; j++) {
        float2 p = unpk_(acc[j]);
        h[j] = sigmoidf_(p.x + p.y + __ldg(b + q * 4 + j));
    }
}

// 3 matvecs + pooling; writes dup'd factors into sMxd[8][128],
// sM2yd[4][128], sMzd[8][128] at column 2r. Thread (r = tid>>2, q = tid&3).
__device__ __forceinline__ void matvec_pool(
    const float* __restrict__ x, const float* __restrict__ y,
    const float* __restrict__ z, int row, float* __restrict__ sMxd,
    float* __restrict__ sM2yd, float* __restrict__ sMzd,
    const float* __restrict__ Wx, const float* __restrict__ bx,
    const float* __restrict__ Wy, const float* __restrict__ by,
    const float* __restrict__ Wz, const float* __restrict__ bz, int r, int q) {
    float h[4];
    mv4(x, row, Wx, bx, q, h);
    st_dup2(sMxd + (2 * q) * 128 + 2 * r, fmaxf(h[0], h[1]));
    st_dup2(sMxd + (2 * q + 1) * 128 + 2 * r, fmaxf(h[2], h[3]));
    mv4(y, row, Wy, by, q, h);
    st_dup2(sM2yd + q * 128 + 2 * r,
            fmaxf(fmaxf(h[0], h[1]), fmaxf(h[2], h[3])));
    mv4(z, row, Wz, bz, q, h);
    st_dup2(sMzd + (2 * q) * 128 + 2 * r, fmaxf(h[0], h[1]));
    st_dup2(sMzd + (2 * q + 1) * 128 + 2 * r, fmaxf(h[2], h[3]));
}

// Fusion GEMM, 4 rows (r0..r0+3) x 4 cols (c0..c0+3), col-pair packed accs.
// F[k = u*8+t][row] = mx[u>>2]*m2y[u&3]*mz[t], weights sW_[k*64 + c].
__device__ __forceinline__ void gemm_fuse(
    const float* __restrict__ sW_, const float* __restrict__ sMxd,
    const float* __restrict__ sM2yd, const float* __restrict__ sMzd, int r0,
    int c0, ull acc[4][2]) {
    ull my2[4][4];
#pragma unroll
    for (int iy = 0; iy < 4; iy++) {
        ulonglong2 ya =
            *reinterpret_cast<const ulonglong2*>(sM2yd + iy * 128 + 2 * r0);
        ulonglong2 yb =
            *reinterpret_cast<const ulonglong2*>(sM2yd + iy * 128 + 2 * r0 + 4);
        my2[iy][0] = ya.x; my2[iy][1] = ya.y;
        my2[iy][2] = yb.x; my2[iy][3] = yb.y;
    }
    const float* zbase = sMzd + 2 * r0;
#pragma unroll 1
    for (int ix = 0; ix < 8; ix++) {
        ulonglong2 ma =
            *reinterpret_cast<const ulonglong2*>(sMxd + ix * 128 + 2 * r0);
        ulonglong2 mb =
            *reinterpret_cast<const ulonglong2*>(sMxd + ix * 128 + 2 * r0 + 4);
#pragma unroll
        for (int iy = 0; iy < 4; iy++) {
            ull P0 = fmul2_(ma.x, my2[iy][0]);
            ull P1 = fmul2_(ma.y, my2[iy][1]);
            ull P2 = fmul2_(mb.x, my2[iy][2]);
            ull P3 = fmul2_(mb.y, my2[iy][3]);
            const float* wrow = sW_ + (ix * 4 + iy) * 512 + c0;
#pragma unroll
            for (int t = 0; t < 8; t++) {
                ulonglong2 za =
                    *reinterpret_cast<const ulonglong2*>(zbase + t * 128);
                ulonglong2 zb =
                    *reinterpret_cast<const ulonglong2*>(zbase + t * 128 + 4);
                ulonglong2 w =
                    *reinterpret_cast<const ulonglong2*>(wrow + t * 64);
                ull f0 = fmul2_(P0, za.x);
                ull f1 = fmul2_(P1, za.y);
                ull f2 = fmul2_(P2, zb.x);
                ull f3 = fmul2_(P3, zb.y);
                ffma2_(acc[0][0], f0, w.x); ffma2_(acc[0][1], f0, w.y);
                ffma2_(acc[1][0], f1, w.x); ffma2_(acc[1][1], f1, w.y);
                ffma2_(acc[2][0], f2, w.x); ffma2_(acc[2][1], f2, w.y);
                ffma2_(acc[3][0], f3, w.x); ffma2_(acc[3][1], f3, w.y);
            }
        }
    }
}

// Shared layout (floats), CORRECT sizes this time:
//  sW    @ 0     : 16384
//  sGT   @ 16384 : 8704   ([128][68])
//  sMxd  @ 25088 : 1024   ([8][128])
//  sM2yd @ 26112 : 512    ([4][128])
//  sMzd  @ 26624 : 1024   ([8][128])
//  total 27648 floats = 110592 B  -> 2 CTAs/SM (221184 B <= 228 KB)
#define OFF_GT 16384
#define OFF_MXD 25088
#define OFF_M2YD 26112
#define OFF_MZD 26624
#define SMEM_FLOATS 27648

__global__ void __launch_bounds__(256, 2) fusion_main(
    const float* __restrict__ a, const float* __restrict__ v,
    const float* __restrict__ l, const float* __restrict__ pa,
    const float* __restrict__ pv, const float* __restrict__ pl,
    const float* __restrict__ mean, const float* __restrict__ Wa,
    const float* __restrict__ ba, const float* __restrict__ Wv,
    const float* __restrict__ bv, const float* __restrict__ Wl,
    const float* __restrict__ bl, const float* __restrict__ Wap,
    const float* __restrict__ bap, const float* __restrict__ Wvp,
    const float* __restrict__ bvp, const float* __restrict__ Wlp,
    const float* __restrict__ blp, const float* __restrict__ bf1,
    const float* __restrict__ bfp1, const float* __restrict__ bng,
    const float* __restrict__ rm1, const float* __restrict__ rm2,
    float* __restrict__ out) {
    extern __shared__ __align__(16) float smem[];
    float* sW_ = smem;
    float* sGT = smem + OFF_GT;
    float* sMxd = smem + OFF_MXD;
    float* sM2yd = smem + OFF_M2YD;
    float* sMzd = smem + OFF_MZD;

    const int tid = threadIdx.x;
    const int row0 = blockIdx.x * 64;
    const int r = tid >> 2, q = tid & 3;  // matvec mapping
    const int r0 = (tid >> 4) * 4;        // GEMM rows
    const int c0 = (tid & 15) * 4;        // GEMM cols

    // ---- P0: Wfp1T -> sW; gated mean -> sGT[64..127]; fusion-2 factors ----
    copy16(sW_, g_WT[0], tid);
#pragma unroll
    for (int it = 0; it < 16; it++) {
        int i = tid + it * 256;
        int rr = i >> 6, cc = i & 63;
        sGT[(64 + cc) * 68 + rr] =
            gatef_(__ldg(mean + (row0 + rr) * 64 + cc), __ldg(rm1 + 64 + cc));
    }
    matvec_pool(pa, pv, pl, row0 + r, sMxd, sM2yd, sMzd, Wap, bap, Wvp, bvp,
                Wlp, blp, r, q);
    __syncthreads();

    // ---- P1: GEMM1 (K=256) -> gate -> sGT[0..63] ----
    {
        ull acc[4][2] = {};
        gemm_fuse(sW_, sMxd, sM2yd, sMzd, r0, c0, acc);
#pragma unroll
        for (int j = 0; j < 2; j++) {
            int ca = c0 + 2 * j, cb = ca + 1;
            float bca = __ldg(bfp1 + ca), bcb = __ldg(bfp1 + cb);
            float rca = __ldg(rm1 + ca), rcb = __ldg(rm1 + cb);
            float2 p0 = unpk_(acc[0][j]), p1 = unpk_(acc[1][j]);
            float2 p2 = unpk_(acc[2][j]), p3 = unpk_(acc[3][j]);
            *reinterpret_cast<float4*>(sGT + ca * 68 + r0) = make_float4(
                gatef_(leakyf_(p0.x + bca), rca), gatef_(leakyf_(p1.x + bca), rca),
                gatef_(leakyf_(p2.x + bca), rca), gatef_(leakyf_(p3.x + bca), rca));
            *reinterpret_cast<float4*>(sGT + cb * 68 + r0) = make_float4(
                gatef_(leakyf_(p0.y + bcb), rcb), gatef_(leakyf_(p1.y + bcb), rcb),
                gatef_(leakyf_(p2.y + bcb), rcb), gatef_(leakyf_(p3.y + bcb), rcb));
        }
    }
    __syncthreads();

    // ---- P2: WngT -> sW[0:8192]; fusion-1 factors ----
    copy8(sW_, g_WngT, tid);
    matvec_pool(a, v, l, row0 + r, sMxd, sM2yd, sMzd, Wa, ba, Wv, bv, Wl, bl,
                r, q);
    __syncthreads();

    // ---- P3: GEMM2 (K=128) -> out[:,0:64]; prefetch Wf1T upper half ----
    {
        ull acc2[4][2] = {};
#pragma unroll 4
        for (int k = 0; k < 128; k++) {
            float4 fv = *reinterpret_cast<const float4*>(sGT + k * 68 + r0);
            ulonglong2 w =
                *reinterpret_cast<const ulonglong2*>(sW_ + k * 64 + c0);
            ull f0 = dup2_(fv.x), f1 = dup2_(fv.y);
            ull f2 = dup2_(fv.z), f3 = dup2_(fv.w);
            ffma2_(acc2[0][0], f0, w.x); ffma2_(acc2[0][1], f0, w.y);
            ffma2_(acc2[1][0], f1, w.x); ffma2_(acc2[1][1], f1, w.y);
            ffma2_(acc2[2][0], f2, w.x); ffma2_(acc2[2][1], f2, w.y);
            ffma2_(acc2[3][0], f3, w.x); ffma2_(acc2[3][1], f3, w.y);
        }
        float4 bb = __ldg(reinterpret_cast<const float4*>(bng + c0));
        float4 rr2 = __ldg(reinterpret_cast<const float4*>(rm2 + c0));
#pragma unroll
        for (int i = 0; i < 4; i++) {
            float2 pA = unpk_(acc2[i][0]), pB = unpk_(acc2[i][1]);
            *reinterpret_cast<float4*>(out + (row0 + r0 + i) * 128 + c0) =
                make_float4(gatef_(pA.x + bb.x, rr2.x),
                            gatef_(pA.y + bb.y, rr2.y),
                            gatef_(pB.x + bb.z, rr2.z),
                            gatef_(pB.y + bb.w, rr2.w));
        }
    }
    copy8(sW_ + 8192, g_WT[1] + 8192, tid);  // upper half of Wf1T
    __syncthreads();

    // ---- P4: lower half of Wf1T -> sW[0:8192] ----
    copy8(sW_, g_WT[1], tid);
    __syncthreads();

    // ---- P5: GEMM3 (K=256) -> out[:,64:128] ----
    {
        ull acc[4][2] = {};
        gemm_fuse(sW_, sMxd, sM2yd, sMzd, r0, c0, acc);
        float4 bb = __ldg(reinterpret_cast<const float4*>(bf1 + c0));
        float4 rr2 = __ldg(reinterpret_cast<const float4*>(rm2 + 64 + c0));
#pragma unroll
        for (int i = 0; i < 4; i++) {
            float2 pA = unpk_(acc[i][0]), pB = unpk_(acc[i][1]);
            *reinterpret_cast<float4*>(out + (row0 + r0 + i) * 128 + 64 + c0) =
                make_float4(gatef_(leakyf_(pA.x + bb.x), rr2.x),
                            gatef_(leakyf_(pA.y + bb.y), rr2.y),
                            gatef_(leakyf_(pB.x + bb.z), rr2.z),
                            gatef_(leakyf_(pB.y + bb.w), rr2.w));
        }
    }
}

extern "C" void kernel_launch(void* const* d_in, const int* in_sizes, int n_in,
                              void* d_out, int out_size) {
    const float* a    = (const float*)d_in[0];
    const float* v    = (const float*)d_in[1];
    const float* l    = (const float*)d_in[2];
    const float* pa   = (const float*)d_in[3];
    const float* pv   = (const float*)d_in[4];
    const float* pl   = (const float*)d_in[5];
    const float* mean = (const float*)d_in[6];
    const float* Wa   = (const float*)d_in[7];
    const float* ba   = (const float*)d_in[8];
    const float* Wv   = (const float*)d_in[9];
    const float* bv   = (const float*)d_in[10];
    const float* Wl   = (const float*)d_in[11];
    const float* bl   = (const float*)d_in[12];
    const float* Wap  = (const float*)d_in[13];
    const float* bap  = (const float*)d_in[14];
    const float* Wvp  = (const float*)d_in[15];
    const float* bvp  = (const float*)d_in[16];
    const float* Wlp  = (const float*)d_in[17];
    const float* blp  = (const float*)d_in[18];
    const float* Wf1  = (const float*)d_in[19];
    const float* bf1  = (const float*)d_in[20];
    const float* Wfp1 = (const float*)d_in[21];
    const float* bfp1 = (const float*)d_in[22];
    const float* Wng  = (const float*)d_in[23];
    const float* bng  = (const float*)d_in[24];
    const float* rm1  = (const float*)d_in[25];
    const float* rm2  = (const float*)d_in[26];

    int nrows = in_sizes[0] / 64;
    static int smem_set = 0;
    if (!smem_set) {
        cudaFuncSetAttribute(fusion_main,
                             cudaFuncAttributeMaxDynamicSharedMemorySize,
                             SMEM_FLOATS * 4);
        smem_set = 1;
    }

    setup_kernel<<<64, 256>>>(Wfp1, Wf1, Wng);
    fusion_main<<<nrows / 64, 256, SMEM_FLOATS * 4>>>(
        a, v, l, pa, pv, pl, mean, Wa, ba, Wv, bv, Wl, bl, Wap, bap, Wvp, bvp,
        Wlp, blp, bf1, bfp1, bng, rm1, rm2, (float*)d_out);
}